// round 1
// baseline (speedup 1.0000x reference)
#include <cuda_runtime.h>
#include <math.h>

// ---------------- problem constants ----------------
#define DM    1024   // d_model
#define SEQ   1024
#define BATCH 8
#define RK    128    // rank
#define NC    64
#define NQK   32
#define NV    32
#define KC    8
#define KQK   4
#define KV    6
#define NHEAD 16
#define DH    64
#define NW    128    // NC + NQK + NV

// ---------------- device scratch (no allocations allowed) ----------------
__device__ float g_prefw[BATCH * SEQ * NW];       // weighted softmax prefs
__device__ float g_acc[BATCH * NW];               // reduced over S
__device__ int   g_cidx[BATCH * KC];
__device__ float g_cval[BATCH * KC];
__device__ int   g_qidx[BATCH * KQK];
__device__ float g_qval[BATCH * KQK];
__device__ int   g_vidx[BATCH * KV];
__device__ float g_vval[BATCH * KV];
__device__ float g_sc [BATCH * DM * RK];          // shared_compress [b][d][r]
__device__ float g_eqk[BATCH * RK * DM];          // [b][r][d]
__device__ float g_ev [BATCH * RK * DM];
__device__ float g_h  [BATCH * SEQ * RK];
__device__ float g_Q  [BATCH * SEQ * DM];
__device__ float g_V  [BATCH * SEQ * DM];
__device__ float g_ao [BATCH * SEQ * DM];         // attention output

// ---------------- router: per-(b,s) softmaxes * importance ----------------
__global__ void router_kernel(const float* __restrict__ x,
                              const float* __restrict__ importance,
                              const float* __restrict__ Wc,
                              const float* __restrict__ Wqk,
                              const float* __restrict__ Wv) {
    int bs = blockIdx.x;            // 0..8191
    int t  = threadIdx.x;           // 0..127
    __shared__ float xs[DM];
    __shared__ float sc[NW];
    __shared__ float es[NW];

    const float4* xg = (const float4*)(x + (size_t)bs * DM);
    float4* xs4 = (float4*)xs;
    for (int i = t; i < DM / 4; i += NW) xs4[i] = xg[i];
    __syncthreads();

    const float* Wrow;
    if (t < NC)            Wrow = Wc  + (size_t)t * DM;
    else if (t < NC + NQK) Wrow = Wqk + (size_t)(t - NC) * DM;
    else                   Wrow = Wv  + (size_t)(t - NC - NQK) * DM;
    const float4* w4 = (const float4*)Wrow;

    float acc = 0.f;
#pragma unroll 8
    for (int i = 0; i < DM / 4; i++) {
        float4 a = xs4[i]; float4 b = w4[i];
        acc = fmaf(a.x, b.x, acc); acc = fmaf(a.y, b.y, acc);
        acc = fmaf(a.z, b.z, acc); acc = fmaf(a.w, b.w, acc);
    }
    sc[t] = acc;
    __syncthreads();

    int g0, gn;
    if (t < NC)            { g0 = 0;        gn = NC;  }
    else if (t < NC + NQK) { g0 = NC;       gn = NQK; }
    else                   { g0 = NC + NQK; gn = NV;  }

    float m = -1e30f;
    for (int i = 0; i < gn; i++) m = fmaxf(m, sc[g0 + i]);
    float e = __expf(acc - m);
    es[t] = e;
    __syncthreads();
    float s = 0.f;
    for (int i = 0; i < gn; i++) s += es[g0 + i];

    float imp = importance[bs];
    g_prefw[(size_t)bs * NW + t] = imp * e / s;
}

// ---------------- reduce over S (deterministic, no atomics) ----------------
__global__ void reduce_kernel() {
    int b = blockIdx.x, t = threadIdx.x;   // t in [0,128)
    const float* p = g_prefw + (size_t)b * SEQ * NW + t;
    float s = 0.f;
    for (int i = 0; i < SEQ; i++) s += p[(size_t)i * NW];
    g_acc[b * NW + t] = s;
}

// ---------------- top-k + renormalize ----------------
__device__ void topk_store(const float* v, int n, int k, int* oidx, float* oval) {
    float tmp[64];
    for (int i = 0; i < n; i++) tmp[i] = v[i];
    float sum = 0.f;
    for (int j = 0; j < k; j++) {
        int bi = 0; float bv = tmp[0];
        for (int i = 1; i < n; i++) { if (tmp[i] > bv) { bv = tmp[i]; bi = i; } }
        oidx[j] = bi; oval[j] = bv; sum += bv;
        tmp[bi] = -1e30f;
    }
    float inv = 1.f / (sum + 1e-8f);
    for (int j = 0; j < k; j++) oval[j] *= inv;
}

__global__ void topk_kernel() {
    int b = blockIdx.x, t = threadIdx.x;
    const float* base = g_acc + b * NW;
    if (t == 0)      topk_store(base,            NC,  KC,  g_cidx + b * KC,  g_cval + b * KC);
    else if (t == 1) topk_store(base + NC,       NQK, KQK, g_qidx + b * KQK, g_qval + b * KQK);
    else if (t == 2) topk_store(base + NC + NQK, NV,  KV,  g_vidx + b * KV,  g_vval + b * KV);
}

// ---------------- sparse weighted mixes ----------------
__global__ void build_sc_kernel(const float* __restrict__ CN) {
    int b = blockIdx.y;
    int i = blockIdx.x * blockDim.x + threadIdx.x;   // 0 .. DM*RK-1
    float s = 0.f;
#pragma unroll
    for (int j = 0; j < KC; j++) {
        int n = g_cidx[b * KC + j];
        s = fmaf(g_cval[b * KC + j], CN[(size_t)n * (DM * RK) + i], s);
    }
    g_sc[(size_t)b * (DM * RK) + i] = s;
}

__global__ void build_eqk_kernel(const float* __restrict__ E) {
    int b = blockIdx.y;
    int i = blockIdx.x * blockDim.x + threadIdx.x;
    float s = 0.f;
#pragma unroll
    for (int j = 0; j < KQK; j++) {
        int n = g_qidx[b * KQK + j];
        s = fmaf(g_qval[b * KQK + j], E[(size_t)n * (RK * DM) + i], s);
    }
    g_eqk[(size_t)b * (RK * DM) + i] = s;
}

__global__ void build_ev_kernel(const float* __restrict__ E) {
    int b = blockIdx.y;
    int i = blockIdx.x * blockDim.x + threadIdx.x;
    float s = 0.f;
#pragma unroll
    for (int j = 0; j < KV; j++) {
        int n = g_vidx[b * KV + j];
        s = fmaf(g_vval[b * KV + j], E[(size_t)n * (RK * DM) + i], s);
    }
    g_ev[(size_t)b * (RK * DM) + i] = s;
}

// ---------------- tiled SGEMM (nn): C = A(MxK) * B(KxN) ----------------
__global__ void sgemm_nn(const float* __restrict__ A, const float* __restrict__ B,
                         float* __restrict__ C, int M, int N, int K,
                         long long sA, long long sB, long long sC) {
    A += (long long)blockIdx.z * sA;
    B += (long long)blockIdx.z * sB;
    C += (long long)blockIdx.z * sC;
    __shared__ float As[16][65];
    __shared__ float Bs[16][65];
    int tid = threadIdx.x;
    int tx = tid & 15, ty = tid >> 4;
    int m0 = blockIdx.y * 64, n0 = blockIdx.x * 64;
    float acc[4][4] = {};

    for (int k0 = 0; k0 < K; k0 += 16) {
#pragma unroll
        for (int i = 0; i < 4; i++) {
            int idx = tid + i * 256;
            int r = idx >> 4, c = idx & 15;
            As[c][r] = A[(size_t)(m0 + r) * K + k0 + c];
        }
#pragma unroll
        for (int i = 0; i < 4; i++) {
            int idx = tid + i * 256;
            int r = idx >> 6, c = idx & 63;
            Bs[r][c] = B[(size_t)(k0 + r) * N + n0 + c];
        }
        __syncthreads();
#pragma unroll
        for (int k = 0; k < 16; k++) {
            float a[4], bb[4];
#pragma unroll
            for (int i = 0; i < 4; i++) a[i]  = As[k][ty * 4 + i];
#pragma unroll
            for (int j = 0; j < 4; j++) bb[j] = Bs[k][tx * 4 + j];
#pragma unroll
            for (int i = 0; i < 4; i++)
#pragma unroll
                for (int j = 0; j < 4; j++)
                    acc[i][j] = fmaf(a[i], bb[j], acc[i][j]);
        }
        __syncthreads();
    }
#pragma unroll
    for (int i = 0; i < 4; i++)
#pragma unroll
        for (int j = 0; j < 4; j++)
            C[(size_t)(m0 + ty * 4 + i) * N + n0 + tx * 4 + j] = acc[i][j];
}

// ---------------- tiled SGEMM (nt): C = A(MxK) * B(NxK)^T ----------------
__global__ void sgemm_nt(const float* __restrict__ A, const float* __restrict__ B,
                         float* __restrict__ C, int M, int N, int K) {
    __shared__ float As[16][65];
    __shared__ float Bs[16][65];
    int tid = threadIdx.x;
    int tx = tid & 15, ty = tid >> 4;
    int m0 = blockIdx.y * 64, n0 = blockIdx.x * 64;
    float acc[4][4] = {};

    for (int k0 = 0; k0 < K; k0 += 16) {
#pragma unroll
        for (int i = 0; i < 4; i++) {
            int idx = tid + i * 256;
            int r = idx >> 4, c = idx & 15;
            As[c][r] = A[(size_t)(m0 + r) * K + k0 + c];
        }
#pragma unroll
        for (int i = 0; i < 4; i++) {
            int idx = tid + i * 256;
            int r = idx >> 4, c = idx & 15;
            Bs[c][r] = B[(size_t)(n0 + r) * K + k0 + c];
        }
        __syncthreads();
#pragma unroll
        for (int k = 0; k < 16; k++) {
            float a[4], bb[4];
#pragma unroll
            for (int i = 0; i < 4; i++) a[i]  = As[k][ty * 4 + i];
#pragma unroll
            for (int j = 0; j < 4; j++) bb[j] = Bs[k][tx * 4 + j];
#pragma unroll
            for (int i = 0; i < 4; i++)
#pragma unroll
                for (int j = 0; j < 4; j++)
                    acc[i][j] = fmaf(a[i], bb[j], acc[i][j]);
        }
        __syncthreads();
    }
#pragma unroll
    for (int i = 0; i < 4; i++)
#pragma unroll
        for (int j = 0; j < 4; j++)
            C[(size_t)(m0 + ty * 4 + i) * N + n0 + tx * 4 + j] = acc[i][j];
}

// ---------------- flash attention (K == Q), causal ----------------
// block = (q_tile, head, batch); 256 threads; 64x64 tiles, dh = 64
__global__ void flash_kernel() {
    extern __shared__ float sm[];
    float* Qs = sm;              // 64*65
    float* Ks = Qs + 64 * 65;
    float* Vs = Ks + 64 * 65;
    float* Ps = Vs + 64 * 65;

    int qt = blockIdx.x, h = blockIdx.y, b = blockIdx.z;
    int tid = threadIdx.x;
    int r  = tid >> 2;           // query row within tile
    int cg = tid & 3;            // column group (16 cols each)

    const float* Qb = g_Q + (size_t)b * SEQ * DM + h * DH;
    const float* Vb = g_V + (size_t)b * SEQ * DM + h * DH;

    for (int i = tid; i < 64 * 64; i += 256) {
        int rr = i >> 6, dd = i & 63;
        Qs[rr * 65 + dd] = Qb[(size_t)(qt * 64 + rr) * DM + dd];
    }

    float o[16];
#pragma unroll
    for (int c = 0; c < 16; c++) o[c] = 0.f;
    float m = -1e30f, l = 0.f;
    const float scale = 0.125f;   // 1/sqrt(64)

    for (int kt = 0; kt <= qt; kt++) {
        __syncthreads();   // protects Qs (1st iter) and Ks/Vs/Ps from prior iter
        for (int i = tid; i < 64 * 64; i += 256) {
            int rr = i >> 6, dd = i & 63;
            Ks[rr * 65 + dd] = Qb[(size_t)(kt * 64 + rr) * DM + dd];
            Vs[rr * 65 + dd] = Vb[(size_t)(kt * 64 + rr) * DM + dd];
        }
        __syncthreads();

        float p[16];
#pragma unroll
        for (int j = 0; j < 16; j++) {
            int col = cg * 16 + j;
            float s = 0.f;
#pragma unroll 8
            for (int d = 0; d < 64; d++)
                s = fmaf(Qs[r * 65 + d], Ks[col * 65 + d], s);
            s *= scale;
            if (kt == qt && col > r) s = -1e30f;
            p[j] = s;
        }

        float rowmax = p[0];
#pragma unroll
        for (int j = 1; j < 16; j++) rowmax = fmaxf(rowmax, p[j]);
        rowmax = fmaxf(rowmax, __shfl_xor_sync(0xffffffffu, rowmax, 1));
        rowmax = fmaxf(rowmax, __shfl_xor_sync(0xffffffffu, rowmax, 2));

        float mnew  = fmaxf(m, rowmax);
        float alpha = __expf(m - mnew);
        float psum = 0.f;
#pragma unroll
        for (int j = 0; j < 16; j++) { p[j] = __expf(p[j] - mnew); psum += p[j]; }
        psum += __shfl_xor_sync(0xffffffffu, psum, 1);
        psum += __shfl_xor_sync(0xffffffffu, psum, 2);

        l = l * alpha + psum;
        m = mnew;
#pragma unroll
        for (int c = 0; c < 16; c++) o[c] *= alpha;

#pragma unroll
        for (int j = 0; j < 16; j++) Ps[r * 65 + cg * 16 + j] = p[j];
        __syncthreads();

#pragma unroll 8
        for (int j = 0; j < 64; j++) {
            float pv = Ps[r * 65 + j];
#pragma unroll
            for (int c = 0; c < 16; c++)
                o[c] = fmaf(pv, Vs[j * 65 + cg * 16 + c], o[c]);
        }
    }

    float inv = 1.f / l;
    float* Ob = g_ao + ((size_t)b * SEQ + qt * 64 + r) * DM + h * DH + cg * 16;
#pragma unroll
    for (int c = 0; c < 16; c++) Ob[c] = o[c] * inv;
}

// ---------------- launch ----------------
extern "C" void kernel_launch(void* const* d_in, const int* in_sizes, int n_in,
                              void* d_out, int out_size) {
    const float* x    = (const float*)d_in[0];
    const float* imp  = (const float*)d_in[1];
    const float* Wc   = (const float*)d_in[2];
    const float* Wqk  = (const float*)d_in[3];
    const float* Wv   = (const float*)d_in[4];
    const float* CN   = (const float*)d_in[5];
    const float* EQK  = (const float*)d_in[6];
    const float* EV   = (const float*)d_in[7];
    const float* Wo   = (const float*)d_in[8];
    float* out = (float*)d_out;

    // resolve device-scratch addresses (pure lookups; capture-safe)
    float *p_sc, *p_eqk, *p_ev, *p_h, *p_Q, *p_V, *p_ao;
    cudaGetSymbolAddress((void**)&p_sc,  g_sc);
    cudaGetSymbolAddress((void**)&p_eqk, g_eqk);
    cudaGetSymbolAddress((void**)&p_ev,  g_ev);
    cudaGetSymbolAddress((void**)&p_h,   g_h);
    cudaGetSymbolAddress((void**)&p_Q,   g_Q);
    cudaGetSymbolAddress((void**)&p_V,   g_V);
    cudaGetSymbolAddress((void**)&p_ao,  g_ao);

    static int smem_set = 0;
    const int flash_smem = 4 * 64 * 65 * (int)sizeof(float);   // 66560 B
    if (!smem_set) {
        cudaFuncSetAttribute(flash_kernel,
                             cudaFuncAttributeMaxDynamicSharedMemorySize, flash_smem);
        smem_set = 1;
    }

    // 1) routers
    router_kernel<<<BATCH * SEQ, NW>>>(x, imp, Wc, Wqk, Wv);
    // 2) deterministic reduction over S
    reduce_kernel<<<BATCH, NW>>>();
    // 3) top-k + renorm
    topk_kernel<<<BATCH, 32>>>();
    // 4) sparse mixes
    build_sc_kernel <<<dim3((DM * RK) / 256, BATCH), 256>>>(CN);
    build_eqk_kernel<<<dim3((RK * DM) / 256, BATCH), 256>>>(EQK);
    build_ev_kernel <<<dim3((RK * DM) / 256, BATCH), 256>>>(EV);
    // 5) h = x @ sc      [1024 x 128 x 1024] per batch
    sgemm_nn<<<dim3(RK / 64, SEQ / 64, BATCH), 256>>>(
        x, p_sc, p_h, SEQ, RK, DM,
        (long long)SEQ * DM, (long long)DM * RK, (long long)SEQ * RK);
    // 6) Q = h @ eqk     [1024 x 1024 x 128] per batch
    sgemm_nn<<<dim3(DM / 64, SEQ / 64, BATCH), 256>>>(
        p_h, p_eqk, p_Q, SEQ, DM, RK,
        (long long)SEQ * RK, (long long)RK * DM, (long long)SEQ * DM);
    // 7) V = h @ ev
    sgemm_nn<<<dim3(DM / 64, SEQ / 64, BATCH), 256>>>(
        p_h, p_ev, p_V, SEQ, DM, RK,
        (long long)SEQ * RK, (long long)RK * DM, (long long)SEQ * DM);
    // 8) causal flash attention (K == Q)
    flash_kernel<<<dim3(SEQ / 64, NHEAD, BATCH), 256, flash_smem>>>();
    // 9) out = ao @ Wo^T   [8192 x 1024 x 1024]
    sgemm_nt<<<dim3(DM / 64, (BATCH * SEQ) / 64, 1), 256>>>(
        p_ao, Wo, out, BATCH * SEQ, DM, DM);
}

// round 2
// speedup vs baseline: 3.9213x; 3.9213x over previous
#include <cuda_runtime.h>
#include <math.h>

// ---------------- problem constants ----------------
#define DM    1024
#define SEQ   1024
#define BATCH 8
#define RK    128
#define NC    64
#define NQK   32
#define NV    32
#define KC    8
#define KQK   4
#define KV    6
#define NHEAD 16
#define DH    64
#define NW    128

// ---------------- device scratch ----------------
__device__ float g_prefw[BATCH * SEQ * NW];
__device__ float g_part[BATCH * 16 * NW];
__device__ float g_acc[BATCH * NW];
__device__ int   g_cidx[BATCH * KC];
__device__ float g_cval[BATCH * KC];
__device__ int   g_qidx[BATCH * KQK];
__device__ float g_qval[BATCH * KQK];
__device__ int   g_vidx[BATCH * KV];
__device__ float g_vval[BATCH * KV];
__device__ float g_sc [BATCH * DM * RK];
__device__ float g_eqk[BATCH * RK * DM];
__device__ float g_ev [BATCH * RK * DM];
__device__ float g_h  [BATCH * SEQ * RK];
__device__ float g_Q  [BATCH * SEQ * DM];
__device__ float g_V  [BATCH * SEQ * DM];
__device__ float g_ao [BATCH * SEQ * DM];

// =====================================================================
// Router GEMM: logits[8192][128] = x @ [Wc;Wqk;Wv]^T, fused softmax
// epilogue (3 groups) * importance, writes g_prefw. BM=128, BN=128, KB=16.
// =====================================================================
__global__ __launch_bounds__(256, 2) void router_gemm(
    const float* __restrict__ x,  const float* __restrict__ Wc,
    const float* __restrict__ Wqk, const float* __restrict__ Wv,
    const float* __restrict__ imp)
{
    __shared__ float As[16][132];
    __shared__ float Bs[16][132];
    int tid = threadIdx.x, tx = tid & 15, ty = tid >> 4;
    int m0 = blockIdx.y * 128;
    float acc[8][8] = {};

    const int nkb = DM / 16;
    float4 pa[2], pb[2];

    auto LD = [&](int kb) {
#pragma unroll
        for (int i = 0; i < 2; i++) {
            int f = tid + i * 256; int r = f >> 2, q = f & 3;
            pa[i] = *(const float4*)&x[(size_t)(m0 + r) * DM + kb * 16 + q * 4];
        }
#pragma unroll
        for (int i = 0; i < 2; i++) {
            int f = tid + i * 256; int n = f >> 2, q = f & 3;
            const float* wrow = (n < NC) ? (Wc + (size_t)n * DM)
                              : (n < NC + NQK) ? (Wqk + (size_t)(n - NC) * DM)
                              : (Wv + (size_t)(n - NC - NQK) * DM);
            pb[i] = *(const float4*)&wrow[kb * 16 + q * 4];
        }
    };
    auto ST = [&]() {
#pragma unroll
        for (int i = 0; i < 2; i++) {
            int f = tid + i * 256; int r = f >> 2, q = f & 3;
            As[q*4+0][r] = pa[i].x; As[q*4+1][r] = pa[i].y;
            As[q*4+2][r] = pa[i].z; As[q*4+3][r] = pa[i].w;
        }
#pragma unroll
        for (int i = 0; i < 2; i++) {
            int f = tid + i * 256; int n = f >> 2, q = f & 3;
            Bs[q*4+0][n] = pb[i].x; Bs[q*4+1][n] = pb[i].y;
            Bs[q*4+2][n] = pb[i].z; Bs[q*4+3][n] = pb[i].w;
        }
    };

    LD(0); ST(); __syncthreads();
    for (int kb = 0; kb < nkb; kb++) {
        bool more = (kb + 1 < nkb);
        if (more) LD(kb + 1);
#pragma unroll
        for (int k = 0; k < 16; k++) {
            float a[8], b[8];
            *(float4*)&a[0] = *(const float4*)&As[k][ty * 4];
            *(float4*)&a[4] = *(const float4*)&As[k][64 + ty * 4];
            *(float4*)&b[0] = *(const float4*)&Bs[k][tx * 4];
            *(float4*)&b[4] = *(const float4*)&Bs[k][64 + tx * 4];
#pragma unroll
            for (int i = 0; i < 8; i++)
#pragma unroll
                for (int j = 0; j < 8; j++)
                    acc[i][j] = fmaf(a[i], b[j], acc[i][j]);
        }
        __syncthreads();
        if (more) { ST(); __syncthreads(); }
    }

    // fused softmax epilogue: cols [0,64)=compress (all 16 tx lanes),
    // cols [64,96)=QK (tx 0..7), cols [96,128)=V (tx 8..15)
#pragma unroll
    for (int i = 0; i < 8; i++) {
        int r = (i < 4) ? (ty * 4 + i) : (64 + ty * 4 + i - 4);
        int bs = m0 + r;
        float mC = fmaxf(fmaxf(acc[i][0], acc[i][1]), fmaxf(acc[i][2], acc[i][3]));
#pragma unroll
        for (int w = 1; w < 16; w <<= 1) mC = fmaxf(mC, __shfl_xor_sync(0xffffffffu, mC, w));
        float e0 = __expf(acc[i][0] - mC), e1 = __expf(acc[i][1] - mC);
        float e2 = __expf(acc[i][2] - mC), e3 = __expf(acc[i][3] - mC);
        float sC = e0 + e1 + e2 + e3;
#pragma unroll
        for (int w = 1; w < 16; w <<= 1) sC += __shfl_xor_sync(0xffffffffu, sC, w);

        float m2 = fmaxf(fmaxf(acc[i][4], acc[i][5]), fmaxf(acc[i][6], acc[i][7]));
#pragma unroll
        for (int w = 1; w < 8; w <<= 1) m2 = fmaxf(m2, __shfl_xor_sync(0xffffffffu, m2, w));
        float f0 = __expf(acc[i][4] - m2), f1 = __expf(acc[i][5] - m2);
        float f2 = __expf(acc[i][6] - m2), f3 = __expf(acc[i][7] - m2);
        float s2 = f0 + f1 + f2 + f3;
#pragma unroll
        for (int w = 1; w < 8; w <<= 1) s2 += __shfl_xor_sync(0xffffffffu, s2, w);

        float ip = imp[bs];
        float iC = ip / sC, i2 = ip / s2;
        float4 o0 = {e0 * iC, e1 * iC, e2 * iC, e3 * iC};
        float4 o1 = {f0 * i2, f1 * i2, f2 * i2, f3 * i2};
        *(float4*)&g_prefw[(size_t)bs * NW + tx * 4]      = o0;
        *(float4*)&g_prefw[(size_t)bs * NW + 64 + tx * 4] = o1;
    }
}

// ---------------- two-stage deterministic reduction over S ----------------
__global__ void reduce1_kernel() {
    int b = blockIdx.x, chunk = blockIdx.y, t = threadIdx.x;
    const float* p = g_prefw + ((size_t)b * SEQ + chunk * 64) * NW + t;
    float s = 0.f;
#pragma unroll 8
    for (int i = 0; i < 64; i++) s += p[(size_t)i * NW];
    g_part[(b * 16 + chunk) * NW + t] = s;
}
__global__ void reduce2_kernel() {
    int b = blockIdx.x, t = threadIdx.x;
    float s = 0.f;
#pragma unroll
    for (int c = 0; c < 16; c++) s += g_part[(b * 16 + c) * NW + t];
    g_acc[b * NW + t] = s;
}

// ---------------- top-k + renormalize ----------------
__device__ void topk_store(const float* v, int n, int k, int* oidx, float* oval) {
    float tmp[64];
    for (int i = 0; i < n; i++) tmp[i] = v[i];
    float sum = 0.f;
    for (int j = 0; j < k; j++) {
        int bi = 0; float bv = tmp[0];
        for (int i = 1; i < n; i++) { if (tmp[i] > bv) { bv = tmp[i]; bi = i; } }
        oidx[j] = bi; oval[j] = bv; sum += bv;
        tmp[bi] = -1e30f;
    }
    float inv = 1.f / (sum + 1e-8f);
    for (int j = 0; j < k; j++) oval[j] *= inv;
}
__global__ void topk_kernel() {
    int b = blockIdx.x, t = threadIdx.x;
    const float* base = g_acc + b * NW;
    if (t == 0)      topk_store(base,            NC,  KC,  g_cidx + b * KC,  g_cval + b * KC);
    else if (t == 1) topk_store(base + NC,       NQK, KQK, g_qidx + b * KQK, g_qval + b * KQK);
    else if (t == 2) topk_store(base + NC + NQK, NV,  KV,  g_vidx + b * KV,  g_vval + b * KV);
}

// ---------------- sparse weighted mixes ----------------
__global__ void build_sc_kernel(const float* __restrict__ CN) {
    int b = blockIdx.y;
    int i = blockIdx.x * blockDim.x + threadIdx.x;
    float s = 0.f;
#pragma unroll
    for (int j = 0; j < KC; j++) {
        int n = g_cidx[b * KC + j];
        s = fmaf(g_cval[b * KC + j], CN[(size_t)n * (DM * RK) + i], s);
    }
    g_sc[(size_t)b * (DM * RK) + i] = s;
}
__global__ void build_eqk_kernel(const float* __restrict__ E) {
    int b = blockIdx.y;
    int i = blockIdx.x * blockDim.x + threadIdx.x;
    float s = 0.f;
#pragma unroll
    for (int j = 0; j < KQK; j++) {
        int n = g_qidx[b * KQK + j];
        s = fmaf(g_qval[b * KQK + j], E[(size_t)n * (RK * DM) + i], s);
    }
    g_eqk[(size_t)b * (RK * DM) + i] = s;
}
__global__ void build_ev_kernel(const float* __restrict__ E) {
    int b = blockIdx.y;
    int i = blockIdx.x * blockDim.x + threadIdx.x;
    float s = 0.f;
#pragma unroll
    for (int j = 0; j < KV; j++) {
        int n = g_vidx[b * KV + j];
        s = fmaf(g_vval[b * KV + j], E[(size_t)n * (RK * DM) + i], s);
    }
    g_ev[(size_t)b * (RK * DM) + i] = s;
}

// =====================================================================
// Generic GEMM: C = A * B (or A * B^T if TB). BN=128 fixed, KB=16,
// 256 threads, micro-tile TMx8 with split-half columns, reg double-buffer.
// =====================================================================
template<int BM, bool TB>
__global__ __launch_bounds__(256, 2) void gemm_kernel(
    const float* __restrict__ A, const float* __restrict__ B,
    float* __restrict__ C, int N, int K,
    long long sA, long long sB, long long sC)
{
    constexpr int TM  = BM / 16;
    constexpr int AF4 = BM / 64;
    __shared__ float As[16][132];
    __shared__ float Bs[16][132];
    A += (long long)blockIdx.z * sA;
    B += (long long)blockIdx.z * sB;
    C += (long long)blockIdx.z * sC;
    int tid = threadIdx.x, tx = tid & 15, ty = tid >> 4;
    int m0 = blockIdx.y * BM, n0 = blockIdx.x * 128;
    float acc[TM][8] = {};
    const int nkb = K / 16;
    float4 pa[AF4], pb[2];

    auto LD = [&](int kb) {
#pragma unroll
        for (int i = 0; i < AF4; i++) {
            int f = tid + i * 256; int r = f >> 2, q = f & 3;
            pa[i] = *(const float4*)&A[(size_t)(m0 + r) * K + kb * 16 + q * 4];
        }
#pragma unroll
        for (int i = 0; i < 2; i++) {
            int f = tid + i * 256;
            if (TB) {
                int n = f >> 2, q = f & 3;
                pb[i] = *(const float4*)&B[(size_t)(n0 + n) * K + kb * 16 + q * 4];
            } else {
                int r = f >> 5, c = f & 31;
                pb[i] = *(const float4*)&B[(size_t)(kb * 16 + r) * N + n0 + c * 4];
            }
        }
    };
    auto ST = [&]() {
#pragma unroll
        for (int i = 0; i < AF4; i++) {
            int f = tid + i * 256; int r = f >> 2, q = f & 3;
            As[q*4+0][r] = pa[i].x; As[q*4+1][r] = pa[i].y;
            As[q*4+2][r] = pa[i].z; As[q*4+3][r] = pa[i].w;
        }
#pragma unroll
        for (int i = 0; i < 2; i++) {
            int f = tid + i * 256;
            if (TB) {
                int n = f >> 2, q = f & 3;
                Bs[q*4+0][n] = pb[i].x; Bs[q*4+1][n] = pb[i].y;
                Bs[q*4+2][n] = pb[i].z; Bs[q*4+3][n] = pb[i].w;
            } else {
                int r = f >> 5, c = f & 31;
                *(float4*)&Bs[r][c * 4] = pb[i];
            }
        }
    };

    LD(0); ST(); __syncthreads();
    for (int kb = 0; kb < nkb; kb++) {
        bool more = (kb + 1 < nkb);
        if (more) LD(kb + 1);
#pragma unroll
        for (int k = 0; k < 16; k++) {
            float a[TM], b[8];
            *(float4*)&a[0] = *(const float4*)&As[k][ty * 4];
            if (BM == 128) *(float4*)&a[4] = *(const float4*)&As[k][64 + ty * 4];
            *(float4*)&b[0] = *(const float4*)&Bs[k][tx * 4];
            *(float4*)&b[4] = *(const float4*)&Bs[k][64 + tx * 4];
#pragma unroll
            for (int i = 0; i < TM; i++)
#pragma unroll
                for (int j = 0; j < 8; j++)
                    acc[i][j] = fmaf(a[i], b[j], acc[i][j]);
        }
        __syncthreads();
        if (more) { ST(); __syncthreads(); }
    }

#pragma unroll
    for (int i = 0; i < TM; i++) {
        int r = (i < 4) ? (ty * 4 + i) : (64 + ty * 4 + i - 4);
        float4 c0 = {acc[i][0], acc[i][1], acc[i][2], acc[i][3]};
        float4 c1 = {acc[i][4], acc[i][5], acc[i][6], acc[i][7]};
        *(float4*)&C[(size_t)(m0 + r) * N + n0 + tx * 4]      = c0;
        *(float4*)&C[(size_t)(m0 + r) * N + n0 + 64 + tx * 4] = c1;
    }
}

// =====================================================================
// Flash attention (K == Q), causal, 64x64 tiles, 4x4 micro-tiles.
// =====================================================================
__global__ __launch_bounds__(256) void flash_kernel() {
    extern __shared__ float sm[];
    float* Qs = sm;                  // 64 x 68
    float* Ks = sm + 64 * 68;
    float* Vs = sm + 2 * 64 * 68;
    float* Ps = sm + 3 * 64 * 68;

    int qt = gridDim.x - 1 - blockIdx.x;   // heavy tiles first
    int h = blockIdx.y, b = blockIdx.z;
    int tid = threadIdx.x, tx = tid & 15, ty = tid >> 4;

    const float* Qb = g_Q + (size_t)b * SEQ * DM + (size_t)h * DH;
    const float* Vb = g_V + (size_t)b * SEQ * DM + (size_t)h * DH;

#pragma unroll
    for (int i = 0; i < 4; i++) {
        int f = tid + i * 256; int r = f >> 4, q = f & 15;
        *(float4*)&Qs[r * 68 + q * 4] =
            *(const float4*)&Qb[(size_t)(qt * 64 + r) * DM + q * 4];
    }

    float m[4], l[4], o[4][4];
#pragma unroll
    for (int i = 0; i < 4; i++) {
        m[i] = -1e30f; l[i] = 0.f;
#pragma unroll
        for (int j = 0; j < 4; j++) o[i][j] = 0.f;
    }

    for (int kt = 0; kt <= qt; kt++) {
        __syncthreads();
#pragma unroll
        for (int i = 0; i < 4; i++) {
            int f = tid + i * 256; int r = f >> 4, q = f & 15;
            *(float4*)&Ks[r * 68 + q * 4] =
                *(const float4*)&Qb[(size_t)(kt * 64 + r) * DM + q * 4];
            *(float4*)&Vs[r * 68 + q * 4] =
                *(const float4*)&Vb[(size_t)(kt * 64 + r) * DM + q * 4];
        }
        __syncthreads();

        float s[4][4] = {};
#pragma unroll
        for (int dc = 0; dc < 16; dc++) {
            float a[4][4], bb[4][4];
#pragma unroll
            for (int i = 0; i < 4; i++)
                *(float4*)&a[i][0] = *(const float4*)&Qs[(ty * 4 + i) * 68 + dc * 4];
#pragma unroll
            for (int j = 0; j < 4; j++)
                *(float4*)&bb[j][0] = *(const float4*)&Ks[(tx + 16 * j) * 68 + dc * 4];
#pragma unroll
            for (int i = 0; i < 4; i++)
#pragma unroll
                for (int j = 0; j < 4; j++)
#pragma unroll
                    for (int d = 0; d < 4; d++)
                        s[i][j] = fmaf(a[i][d], bb[j][d], s[i][j]);
        }

        const float scale = 0.125f;
        bool diag = (kt == qt);
        float p[4][4];
#pragma unroll
        for (int i = 0; i < 4; i++) {
            int row = ty * 4 + i;
#pragma unroll
            for (int j = 0; j < 4; j++) {
                float v = s[i][j] * scale;
                if (diag && (tx + 16 * j) > row) v = -1e30f;
                p[i][j] = v;
            }
            float rm = fmaxf(fmaxf(p[i][0], p[i][1]), fmaxf(p[i][2], p[i][3]));
#pragma unroll
            for (int w = 1; w < 16; w <<= 1) rm = fmaxf(rm, __shfl_xor_sync(0xffffffffu, rm, w));
            float mn = fmaxf(m[i], rm);
            float al = __expf(m[i] - mn);
            float ps = 0.f;
#pragma unroll
            for (int j = 0; j < 4; j++) { p[i][j] = __expf(p[i][j] - mn); ps += p[i][j]; }
#pragma unroll
            for (int w = 1; w < 16; w <<= 1) ps += __shfl_xor_sync(0xffffffffu, ps, w);
            l[i] = l[i] * al + ps; m[i] = mn;
#pragma unroll
            for (int j = 0; j < 4; j++) o[i][j] *= al;
        }
#pragma unroll
        for (int i = 0; i < 4; i++)
#pragma unroll
            for (int j = 0; j < 4; j++)
                Ps[(ty * 4 + i) * 68 + tx + 16 * j] = p[i][j];
        __syncthreads();

#pragma unroll
        for (int kc = 0; kc < 16; kc++) {
            float pp[4][4];
#pragma unroll
            for (int i = 0; i < 4; i++)
                *(float4*)&pp[i][0] = *(const float4*)&Ps[(ty * 4 + i) * 68 + kc * 4];
#pragma unroll
            for (int kk = 0; kk < 4; kk++) {
                float v[4];
                *(float4*)&v[0] = *(const float4*)&Vs[(kc * 4 + kk) * 68 + tx * 4];
#pragma unroll
                for (int i = 0; i < 4; i++)
#pragma unroll
                    for (int j = 0; j < 4; j++)
                        o[i][j] = fmaf(pp[i][kk], v[j], o[i][j]);
            }
        }
    }

#pragma unroll
    for (int i = 0; i < 4; i++) {
        float inv = 1.f / l[i];
        float4 r4 = {o[i][0] * inv, o[i][1] * inv, o[i][2] * inv, o[i][3] * inv};
        float* Ob = g_ao + ((size_t)b * SEQ + qt * 64 + ty * 4 + i) * DM
                    + (size_t)h * DH + tx * 4;
        *(float4*)Ob = r4;
    }
}

// ---------------- launch ----------------
extern "C" void kernel_launch(void* const* d_in, const int* in_sizes, int n_in,
                              void* d_out, int out_size) {
    const float* x   = (const float*)d_in[0];
    const float* imp = (const float*)d_in[1];
    const float* Wc  = (const float*)d_in[2];
    const float* Wqk = (const float*)d_in[3];
    const float* Wv  = (const float*)d_in[4];
    const float* CN  = (const float*)d_in[5];
    const float* EQK = (const float*)d_in[6];
    const float* EV  = (const float*)d_in[7];
    const float* Wo  = (const float*)d_in[8];
    float* out = (float*)d_out;

    float *p_sc, *p_eqk, *p_ev, *p_h, *p_Q, *p_V, *p_ao;
    cudaGetSymbolAddress((void**)&p_sc,  g_sc);
    cudaGetSymbolAddress((void**)&p_eqk, g_eqk);
    cudaGetSymbolAddress((void**)&p_ev,  g_ev);
    cudaGetSymbolAddress((void**)&p_h,   g_h);
    cudaGetSymbolAddress((void**)&p_Q,   g_Q);
    cudaGetSymbolAddress((void**)&p_V,   g_V);
    cudaGetSymbolAddress((void**)&p_ao,  g_ao);

    static int smem_set = 0;
    const int flash_smem = 4 * 64 * 68 * (int)sizeof(float);   // 69632 B
    if (!smem_set) {
        cudaFuncSetAttribute(flash_kernel,
                             cudaFuncAttributeMaxDynamicSharedMemorySize, flash_smem);
        smem_set = 1;
    }

    // 1) router GEMM + fused softmax*importance
    router_gemm<<<dim3(1, (BATCH * SEQ) / 128), 256>>>(x, Wc, Wqk, Wv, imp);
    // 2) two-stage deterministic reduction over S
    reduce1_kernel<<<dim3(BATCH, 16), NW>>>();
    reduce2_kernel<<<BATCH, NW>>>();
    // 3) top-k + renorm
    topk_kernel<<<BATCH, 32>>>();
    // 4) sparse mixes
    build_sc_kernel <<<dim3((DM * RK) / 256, BATCH), 256>>>(CN);
    build_eqk_kernel<<<dim3((RK * DM) / 256, BATCH), 256>>>(EQK);
    build_ev_kernel <<<dim3((RK * DM) / 256, BATCH), 256>>>(EV);
    // 5) h = x @ sc   [1024 x 128 x 1024] per batch, BM=64 for occupancy
    gemm_kernel<64, false><<<dim3(1, SEQ / 64, BATCH), 256>>>(
        x, p_sc, p_h, RK, DM,
        (long long)SEQ * DM, (long long)DM * RK, (long long)SEQ * RK);
    // 6) Q = h @ eqk  [1024 x 1024 x 128] per batch
    gemm_kernel<128, false><<<dim3(DM / 128, SEQ / 128, BATCH), 256>>>(
        p_h, p_eqk, p_Q, DM, RK,
        (long long)SEQ * RK, (long long)RK * DM, (long long)SEQ * DM);
    // 7) V = h @ ev
    gemm_kernel<128, false><<<dim3(DM / 128, SEQ / 128, BATCH), 256>>>(
        p_h, p_ev, p_V, DM, RK,
        (long long)SEQ * RK, (long long)RK * DM, (long long)SEQ * DM);
    // 8) flash attention
    flash_kernel<<<dim3(SEQ / 64, NHEAD, BATCH), 256, flash_smem>>>();
    // 9) out = ao @ Wo^T  [8192 x 1024 x 1024]
    gemm_kernel<128, true><<<dim3(DM / 128, (BATCH * SEQ) / 128, 1), 256>>>(
        p_ao, Wo, out, DM, DM, 0, 0, 0);
}

// round 4
// speedup vs baseline: 6.8583x; 1.7490x over previous
#include <cuda_runtime.h>
#include <math.h>
#include <stdint.h>

// ---------------- problem constants ----------------
#define DM    1024
#define SEQ   1024
#define BATCH 8
#define RK    128
#define NC    64
#define NQK   32
#define NV    32
#define KC    8
#define KQK   4
#define KV    6
#define NHEAD 16
#define DH    64
#define NW    128

// ---------------- device scratch ----------------
__device__ float g_prefw[BATCH * SEQ * NW];
__device__ float g_part[BATCH * 16 * NW];
__device__ float g_acc[BATCH * NW];
__device__ int   g_cidx[BATCH * KC];
__device__ float g_cval[BATCH * KC];
__device__ int   g_qidx[BATCH * KQK];
__device__ float g_qval[BATCH * KQK];
__device__ int   g_vidx[BATCH * KV];
__device__ float g_vval[BATCH * KV];
__device__ float g_sc [BATCH * DM * RK];
__device__ float g_eqk[BATCH * RK * DM];
__device__ float g_ev [BATCH * RK * DM];
__device__ float g_h  [BATCH * SEQ * RK];
__device__ float g_Q  [BATCH * SEQ * DM];
__device__ float g_V  [BATCH * SEQ * DM];
__device__ float g_ao [BATCH * SEQ * DM];

// ---------------- tf32 helpers ----------------
__device__ __forceinline__ uint32_t f2tf(float x) {
    uint32_t r;
    asm("cvt.rna.tf32.f32 %0, %1;" : "=r"(r) : "f"(x));
    return r;
}
__device__ __forceinline__ void mma_tf32(float4& d, const uint32_t a[4], const uint32_t b[2]) {
    asm volatile(
        "mma.sync.aligned.m16n8k8.row.col.f32.tf32.tf32.f32 "
        "{%0,%1,%2,%3}, {%4,%5,%6,%7}, {%8,%9}, {%0,%1,%2,%3};\n"
        : "+f"(d.x), "+f"(d.y), "+f"(d.z), "+f"(d.w)
        : "r"(a[0]), "r"(a[1]), "r"(a[2]), "r"(a[3]), "r"(b[0]), "r"(b[1]));
}

// =====================================================================
// Router GEMM (fp32): logits = x @ [Wc;Wqk;Wv]^T, fused softmax*importance
// =====================================================================
__global__ __launch_bounds__(256, 2) void router_gemm(
    const float* __restrict__ x,  const float* __restrict__ Wc,
    const float* __restrict__ Wqk, const float* __restrict__ Wv,
    const float* __restrict__ imp)
{
    __shared__ float As[16][132];
    __shared__ float Bs[16][132];
    int tid = threadIdx.x, tx = tid & 15, ty = tid >> 4;
    int m0 = blockIdx.y * 128;
    float acc[8][8] = {};
    const int nkb = DM / 16;
    float4 pa[2], pb[2];

    auto LD = [&](int kb) {
#pragma unroll
        for (int i = 0; i < 2; i++) {
            int f = tid + i * 256; int r = f >> 2, q = f & 3;
            pa[i] = *(const float4*)&x[(size_t)(m0 + r) * DM + kb * 16 + q * 4];
        }
#pragma unroll
        for (int i = 0; i < 2; i++) {
            int f = tid + i * 256; int n = f >> 2, q = f & 3;
            const float* wrow = (n < NC) ? (Wc + (size_t)n * DM)
                              : (n < NC + NQK) ? (Wqk + (size_t)(n - NC) * DM)
                              : (Wv + (size_t)(n - NC - NQK) * DM);
            pb[i] = *(const float4*)&wrow[kb * 16 + q * 4];
        }
    };
    auto ST = [&]() {
#pragma unroll
        for (int i = 0; i < 2; i++) {
            int f = tid + i * 256; int r = f >> 2, q = f & 3;
            As[q*4+0][r] = pa[i].x; As[q*4+1][r] = pa[i].y;
            As[q*4+2][r] = pa[i].z; As[q*4+3][r] = pa[i].w;
        }
#pragma unroll
        for (int i = 0; i < 2; i++) {
            int f = tid + i * 256; int n = f >> 2, q = f & 3;
            Bs[q*4+0][n] = pb[i].x; Bs[q*4+1][n] = pb[i].y;
            Bs[q*4+2][n] = pb[i].z; Bs[q*4+3][n] = pb[i].w;
        }
    };

    LD(0); ST(); __syncthreads();
    for (int kb = 0; kb < nkb; kb++) {
        bool more = (kb + 1 < nkb);
        if (more) LD(kb + 1);
#pragma unroll
        for (int k = 0; k < 16; k++) {
            float a[8], b[8];
            *(float4*)&a[0] = *(const float4*)&As[k][ty * 4];
            *(float4*)&a[4] = *(const float4*)&As[k][64 + ty * 4];
            *(float4*)&b[0] = *(const float4*)&Bs[k][tx * 4];
            *(float4*)&b[4] = *(const float4*)&Bs[k][64 + tx * 4];
#pragma unroll
            for (int i = 0; i < 8; i++)
#pragma unroll
                for (int j = 0; j < 8; j++)
                    acc[i][j] = fmaf(a[i], b[j], acc[i][j]);
        }
        __syncthreads();
        if (more) { ST(); __syncthreads(); }
    }

#pragma unroll
    for (int i = 0; i < 8; i++) {
        int r = (i < 4) ? (ty * 4 + i) : (64 + ty * 4 + i - 4);
        int bs = m0 + r;
        float mC = fmaxf(fmaxf(acc[i][0], acc[i][1]), fmaxf(acc[i][2], acc[i][3]));
#pragma unroll
        for (int w = 1; w < 16; w <<= 1) mC = fmaxf(mC, __shfl_xor_sync(0xffffffffu, mC, w));
        float e0 = __expf(acc[i][0] - mC), e1 = __expf(acc[i][1] - mC);
        float e2 = __expf(acc[i][2] - mC), e3 = __expf(acc[i][3] - mC);
        float sC = e0 + e1 + e2 + e3;
#pragma unroll
        for (int w = 1; w < 16; w <<= 1) sC += __shfl_xor_sync(0xffffffffu, sC, w);

        float m2 = fmaxf(fmaxf(acc[i][4], acc[i][5]), fmaxf(acc[i][6], acc[i][7]));
#pragma unroll
        for (int w = 1; w < 8; w <<= 1) m2 = fmaxf(m2, __shfl_xor_sync(0xffffffffu, m2, w));
        float f0 = __expf(acc[i][4] - m2), f1 = __expf(acc[i][5] - m2);
        float f2 = __expf(acc[i][6] - m2), f3 = __expf(acc[i][7] - m2);
        float s2 = f0 + f1 + f2 + f3;
#pragma unroll
        for (int w = 1; w < 8; w <<= 1) s2 += __shfl_xor_sync(0xffffffffu, s2, w);

        float ip = imp[bs];
        float iC = ip / sC, i2 = ip / s2;
        float4 o0 = {e0 * iC, e1 * iC, e2 * iC, e3 * iC};
        float4 o1 = {f0 * i2, f1 * i2, f2 * i2, f3 * i2};
        *(float4*)&g_prefw[(size_t)bs * NW + tx * 4]      = o0;
        *(float4*)&g_prefw[(size_t)bs * NW + 64 + tx * 4] = o1;
    }
}

// ---------------- two-stage deterministic reduction over S ----------------
__global__ void reduce1_kernel() {
    int b = blockIdx.x, chunk = blockIdx.y, t = threadIdx.x;
    const float* p = g_prefw + ((size_t)b * SEQ + chunk * 64) * NW + t;
    float s = 0.f;
#pragma unroll 8
    for (int i = 0; i < 64; i++) s += p[(size_t)i * NW];
    g_part[(b * 16 + chunk) * NW + t] = s;
}
__global__ void reduce2_kernel() {
    int b = blockIdx.x, t = threadIdx.x;
    float s = 0.f;
#pragma unroll
    for (int c = 0; c < 16; c++) s += g_part[(b * 16 + c) * NW + t];
    g_acc[b * NW + t] = s;
}

// ---------------- top-k + renormalize ----------------
__device__ void topk_store(const float* v, int n, int k, int* oidx, float* oval) {
    float tmp[64];
    for (int i = 0; i < n; i++) tmp[i] = v[i];
    float sum = 0.f;
    for (int j = 0; j < k; j++) {
        int bi = 0; float bv = tmp[0];
        for (int i = 1; i < n; i++) { if (tmp[i] > bv) { bv = tmp[i]; bi = i; } }
        oidx[j] = bi; oval[j] = bv; sum += bv;
        tmp[bi] = -1e30f;
    }
    float inv = 1.f / (sum + 1e-8f);
    for (int j = 0; j < k; j++) oval[j] *= inv;
}
__global__ void topk_kernel() {
    int b = blockIdx.x, t = threadIdx.x;
    const float* base = g_acc + b * NW;
    if (t == 0)      topk_store(base,            NC,  KC,  g_cidx + b * KC,  g_cval + b * KC);
    else if (t == 1) topk_store(base + NC,       NQK, KQK, g_qidx + b * KQK, g_qval + b * KQK);
    else if (t == 2) topk_store(base + NC + NQK, NV,  KV,  g_vidx + b * KV,  g_vval + b * KV);
}

// ---------------- sparse weighted mixes ----------------
__global__ void build_sc_kernel(const float* __restrict__ CN) {
    int b = blockIdx.y;
    int i = blockIdx.x * blockDim.x + threadIdx.x;
    float s = 0.f;
#pragma unroll
    for (int j = 0; j < KC; j++) {
        int n = g_cidx[b * KC + j];
        s = fmaf(g_cval[b * KC + j], CN[(size_t)n * (DM * RK) + i], s);
    }
    g_sc[(size_t)b * (DM * RK) + i] = s;
}
__global__ void build_eqk_kernel(const float* __restrict__ E) {
    int b = blockIdx.y;
    int i = blockIdx.x * blockDim.x + threadIdx.x;
    float s = 0.f;
#pragma unroll
    for (int j = 0; j < KQK; j++) {
        int n = g_qidx[b * KQK + j];
        s = fmaf(g_qval[b * KQK + j], E[(size_t)n * (RK * DM) + i], s);
    }
    g_eqk[(size_t)b * (RK * DM) + i] = s;
}
__global__ void build_ev_kernel(const float* __restrict__ E) {
    int b = blockIdx.y;
    int i = blockIdx.x * blockDim.x + threadIdx.x;
    float s = 0.f;
#pragma unroll
    for (int j = 0; j < KV; j++) {
        int n = g_vidx[b * KV + j];
        s = fmaf(g_vval[b * KV + j], E[(size_t)n * (RK * DM) + i], s);
    }
    g_ev[(size_t)b * (RK * DM) + i] = s;
}

// =====================================================================
// fp32 GEMM (nn): used for h = x@sc and Q/V = h@e
// =====================================================================
template<int BM>
__global__ __launch_bounds__(256, 2) void gemm_kernel(
    const float* __restrict__ A, const float* __restrict__ B,
    float* __restrict__ C, int N, int K,
    long long sA, long long sB, long long sC)
{
    constexpr int TM  = BM / 16;
    constexpr int AF4 = BM / 64;
    __shared__ float As[16][132];
    __shared__ float Bs[16][132];
    A += (long long)blockIdx.z * sA;
    B += (long long)blockIdx.z * sB;
    C += (long long)blockIdx.z * sC;
    int tid = threadIdx.x, tx = tid & 15, ty = tid >> 4;
    int m0 = blockIdx.y * BM, n0 = blockIdx.x * 128;
    float acc[TM][8] = {};
    const int nkb = K / 16;
    float4 pa[AF4], pb[2];

    auto LD = [&](int kb) {
#pragma unroll
        for (int i = 0; i < AF4; i++) {
            int f = tid + i * 256; int r = f >> 2, q = f & 3;
            pa[i] = *(const float4*)&A[(size_t)(m0 + r) * K + kb * 16 + q * 4];
        }
#pragma unroll
        for (int i = 0; i < 2; i++) {
            int f = tid + i * 256;
            int r = f >> 5, c = f & 31;
            pb[i] = *(const float4*)&B[(size_t)(kb * 16 + r) * N + n0 + c * 4];
        }
    };
    auto ST = [&]() {
#pragma unroll
        for (int i = 0; i < AF4; i++) {
            int f = tid + i * 256; int r = f >> 2, q = f & 3;
            As[q*4+0][r] = pa[i].x; As[q*4+1][r] = pa[i].y;
            As[q*4+2][r] = pa[i].z; As[q*4+3][r] = pa[i].w;
        }
#pragma unroll
        for (int i = 0; i < 2; i++) {
            int f = tid + i * 256;
            int r = f >> 5, c = f & 31;
            *(float4*)&Bs[r][c * 4] = pb[i];
        }
    };

    LD(0); ST(); __syncthreads();
    for (int kb = 0; kb < nkb; kb++) {
        bool more = (kb + 1 < nkb);
        if (more) LD(kb + 1);
#pragma unroll
        for (int k = 0; k < 16; k++) {
            float a[TM], b[8];
            *(float4*)&a[0] = *(const float4*)&As[k][ty * 4];
            if (BM == 128) *(float4*)&a[4] = *(const float4*)&As[k][64 + ty * 4];
            *(float4*)&b[0] = *(const float4*)&Bs[k][tx * 4];
            *(float4*)&b[4] = *(const float4*)&Bs[k][64 + tx * 4];
#pragma unroll
            for (int i = 0; i < TM; i++)
#pragma unroll
                for (int j = 0; j < 8; j++)
                    acc[i][j] = fmaf(a[i], b[j], acc[i][j]);
        }
        __syncthreads();
        if (more) { ST(); __syncthreads(); }
    }

#pragma unroll
    for (int i = 0; i < TM; i++) {
        int r = (i < 4) ? (ty * 4 + i) : (64 + ty * 4 + i - 4);
        float4 c0 = {acc[i][0], acc[i][1], acc[i][2], acc[i][3]};
        float4 c1 = {acc[i][4], acc[i][5], acc[i][6], acc[i][7]};
        *(float4*)&C[(size_t)(m0 + r) * N + n0 + tx * 4]      = c0;
        *(float4*)&C[(size_t)(m0 + r) * N + n0 + 64 + tx * 4] = c1;
    }
}

// =====================================================================
// Out-projection: C = A(8192x1024) @ Wo^T via tf32 mma.sync.
// BM=BN=128, BK=16, 8 warps (4m x 2n), warp tile 32x64 (2x8 atoms).
// =====================================================================
__global__ __launch_bounds__(256, 2) void gemm_nt_mma(
    const float* __restrict__ A, const float* __restrict__ B,
    float* __restrict__ C, int N, int K)
{
    __shared__ uint32_t As[128 * 20];
    __shared__ uint32_t Bs[128 * 20];
    int tid = threadIdx.x, lane = tid & 31, w = tid >> 5;
    int gq = lane >> 2, qd = lane & 3;
    int wm = w & 3, wn = w >> 2;
    int m0 = blockIdx.y * 128, n0 = blockIdx.x * 128;

    float4 acc[2][8];
#pragma unroll
    for (int i = 0; i < 2; i++)
#pragma unroll
        for (int j = 0; j < 8; j++) acc[i][j] = make_float4(0.f, 0.f, 0.f, 0.f);

    const int nkb = K / 16;
    float4 pa[2], pb[2];

    auto LD = [&](int kb) {
#pragma unroll
        for (int i = 0; i < 2; i++) {
            int f = tid + i * 256; int r = f >> 2, q = f & 3;
            pa[i] = *(const float4*)&A[(size_t)(m0 + r) * K + kb * 16 + q * 4];
            pb[i] = *(const float4*)&B[(size_t)(n0 + r) * K + kb * 16 + q * 4];
        }
    };
    auto ST = [&]() {
#pragma unroll
        for (int i = 0; i < 2; i++) {
            int f = tid + i * 256; int r = f >> 2, q = f & 3;
            uint32_t* da = &As[r * 20 + q * 4];
            da[0] = f2tf(pa[i].x); da[1] = f2tf(pa[i].y);
            da[2] = f2tf(pa[i].z); da[3] = f2tf(pa[i].w);
            uint32_t* db = &Bs[r * 20 + q * 4];
            db[0] = f2tf(pb[i].x); db[1] = f2tf(pb[i].y);
            db[2] = f2tf(pb[i].z); db[3] = f2tf(pb[i].w);
        }
    };

    LD(0); ST(); __syncthreads();
    for (int kb = 0; kb < nkb; kb++) {
        bool more = (kb + 1 < nkb);
        if (more) LD(kb + 1);
#pragma unroll
        for (int s = 0; s < 2; s++) {
            int kbs = s * 8;
            uint32_t af[2][4];
#pragma unroll
            for (int i = 0; i < 2; i++) {
                int r = wm * 32 + i * 16 + gq;
                af[i][0] = As[r * 20 + kbs + qd];
                af[i][1] = As[(r + 8) * 20 + kbs + qd];
                af[i][2] = As[r * 20 + kbs + qd + 4];
                af[i][3] = As[(r + 8) * 20 + kbs + qd + 4];
            }
            uint32_t bf[8][2];
#pragma unroll
            for (int j = 0; j < 8; j++) {
                int n = wn * 64 + j * 8 + gq;
                bf[j][0] = Bs[n * 20 + kbs + qd];
                bf[j][1] = Bs[n * 20 + kbs + qd + 4];
            }
#pragma unroll
            for (int i = 0; i < 2; i++)
#pragma unroll
                for (int j = 0; j < 8; j++)
                    mma_tf32(acc[i][j], af[i], bf[j]);
        }
        __syncthreads();
        if (more) { ST(); __syncthreads(); }
    }

#pragma unroll
    for (int i = 0; i < 2; i++) {
        int r0 = m0 + wm * 32 + i * 16 + gq;
#pragma unroll
        for (int j = 0; j < 8; j++) {
            int c0 = n0 + wn * 64 + j * 8 + 2 * qd;
            *(float2*)&C[(size_t)r0 * N + c0]       = make_float2(acc[i][j].x, acc[i][j].y);
            *(float2*)&C[(size_t)(r0 + 8) * N + c0] = make_float2(acc[i][j].z, acc[i][j].w);
        }
    }
}

// =====================================================================
// Flash attention (K==Q), causal, tf32 mma. 64-row q-tiles, 4 warps.
// Warp w owns rows 16w..16w+15. Per kv tile: S=Q@K^T then P@V, both mma.
// smem: Qs/Ps 64x68, Ks 64x68, Vs 64x72 (pads -> conflict-free frag LDS)
// =====================================================================
__global__ __launch_bounds__(128) void flash_mma() {
    extern __shared__ uint32_t sm[];
    uint32_t* Qs = sm;                 // 64 x 68 (reused for P after Q frags load)
    uint32_t* Ks = sm + 64 * 68;
    uint32_t* Vs = sm + 2 * 64 * 68;   // 64 x 72

    int qt = gridDim.x - 1 - blockIdx.x;   // heavy tiles first
    int h = blockIdx.y, b = blockIdx.z;
    int tid = threadIdx.x, lane = tid & 31, w = tid >> 5;
    int gq = lane >> 2, qd = lane & 3;

    const float* Qb = g_Q + (size_t)b * SEQ * DM + (size_t)h * DH;
    const float* Vb = g_V + (size_t)b * SEQ * DM + (size_t)h * DH;

    // stage Q (tf32)
    for (int f = tid; f < 64 * 16; f += 128) {
        int r = f >> 4, q = f & 15;
        float4 v = *(const float4*)&Qb[(size_t)(qt * 64 + r) * DM + q * 4];
        uint32_t* d = &Qs[r * 68 + q * 4];
        d[0] = f2tf(v.x); d[1] = f2tf(v.y); d[2] = f2tf(v.z); d[3] = f2tf(v.w);
    }
    __syncthreads();

    // Q fragments, register resident
    uint32_t qa[8][4];
    int qr = w * 16 + gq;
#pragma unroll
    for (int ka = 0; ka < 8; ka++) {
        qa[ka][0] = Qs[qr * 68 + ka * 8 + qd];
        qa[ka][1] = Qs[(qr + 8) * 68 + ka * 8 + qd];
        qa[ka][2] = Qs[qr * 68 + ka * 8 + qd + 4];
        qa[ka][3] = Qs[(qr + 8) * 68 + ka * 8 + qd + 4];
    }

    float mr0 = -1e30f, mr1 = -1e30f, lr0 = 0.f, lr1 = 0.f;
    float4 oacc[8];
#pragma unroll
    for (int j = 0; j < 8; j++) oacc[j] = make_float4(0.f, 0.f, 0.f, 0.f);

    int row0 = qt * 64 + w * 16 + gq;
    int row1 = row0 + 8;
    const float scale = 0.125f;

    for (int kt = 0; kt <= qt; kt++) {
        __syncthreads();   // prev PV reads done
        for (int f = tid; f < 64 * 16; f += 128) {
            int r = f >> 4, q = f & 15;
            float4 kv = *(const float4*)&Qb[(size_t)(kt * 64 + r) * DM + q * 4];
            uint32_t* dk = &Ks[r * 68 + q * 4];
            dk[0] = f2tf(kv.x); dk[1] = f2tf(kv.y); dk[2] = f2tf(kv.z); dk[3] = f2tf(kv.w);
            float4 vv = *(const float4*)&Vb[(size_t)(kt * 64 + r) * DM + q * 4];
            uint32_t* dv = &Vs[r * 72 + q * 4];
            dv[0] = f2tf(vv.x); dv[1] = f2tf(vv.y); dv[2] = f2tf(vv.z); dv[3] = f2tf(vv.w);
        }
        __syncthreads();

        // S = Q @ K^T
        float4 sacc[8];
#pragma unroll
        for (int j = 0; j < 8; j++) sacc[j] = make_float4(0.f, 0.f, 0.f, 0.f);
#pragma unroll
        for (int ka = 0; ka < 8; ka++) {
#pragma unroll
            for (int j = 0; j < 8; j++) {
                uint32_t bb[2];
                bb[0] = Ks[(j * 8 + gq) * 68 + ka * 8 + qd];
                bb[1] = Ks[(j * 8 + gq) * 68 + ka * 8 + qd + 4];
                mma_tf32(sacc[j], qa[ka], bb);
            }
        }

        // scale + causal mask + online softmax
        bool diag = (kt == qt);
        float p0[8], p1[8], p2[8], p3[8];
        float mx0 = -1e30f, mx1 = -1e30f;
#pragma unroll
        for (int j = 0; j < 8; j++) {
            int col = kt * 64 + j * 8 + 2 * qd;
            float c0 = sacc[j].x * scale, c1 = sacc[j].y * scale;
            float c2 = sacc[j].z * scale, c3 = sacc[j].w * scale;
            if (diag) {
                if (col     > row0) c0 = -1e30f;
                if (col + 1 > row0) c1 = -1e30f;
                if (col     > row1) c2 = -1e30f;
                if (col + 1 > row1) c3 = -1e30f;
            }
            p0[j] = c0; p1[j] = c1; p2[j] = c2; p3[j] = c3;
            mx0 = fmaxf(mx0, fmaxf(c0, c1));
            mx1 = fmaxf(mx1, fmaxf(c2, c3));
        }
        mx0 = fmaxf(mx0, __shfl_xor_sync(0xffffffffu, mx0, 1));
        mx0 = fmaxf(mx0, __shfl_xor_sync(0xffffffffu, mx0, 2));
        mx1 = fmaxf(mx1, __shfl_xor_sync(0xffffffffu, mx1, 1));
        mx1 = fmaxf(mx1, __shfl_xor_sync(0xffffffffu, mx1, 2));

        float mn0 = fmaxf(mr0, mx0), mn1 = fmaxf(mr1, mx1);
        float al0 = __expf(mr0 - mn0), al1 = __expf(mr1 - mn1);
        float ps0 = 0.f, ps1 = 0.f;
#pragma unroll
        for (int j = 0; j < 8; j++) {
            p0[j] = __expf(p0[j] - mn0); p1[j] = __expf(p1[j] - mn0);
            p2[j] = __expf(p2[j] - mn1); p3[j] = __expf(p3[j] - mn1);
            ps0 += p0[j] + p1[j];
            ps1 += p2[j] + p3[j];
        }
        ps0 += __shfl_xor_sync(0xffffffffu, ps0, 1);
        ps0 += __shfl_xor_sync(0xffffffffu, ps0, 2);
        ps1 += __shfl_xor_sync(0xffffffffu, ps1, 1);
        ps1 += __shfl_xor_sync(0xffffffffu, ps1, 2);

        lr0 = lr0 * al0 + ps0; lr1 = lr1 * al1 + ps1;
        mr0 = mn0; mr1 = mn1;
#pragma unroll
        for (int j = 0; j < 8; j++) {
            oacc[j].x *= al0; oacc[j].y *= al0;
            oacc[j].z *= al1; oacc[j].w *= al1;
        }

        // store P (tf32) into Qs (=Ps)
        int pr0 = w * 16 + gq;
#pragma unroll
        for (int j = 0; j < 8; j++) {
            int cl = j * 8 + 2 * qd;
            Qs[pr0 * 68 + cl]           = f2tf(p0[j]);
            Qs[pr0 * 68 + cl + 1]       = f2tf(p1[j]);
            Qs[(pr0 + 8) * 68 + cl]     = f2tf(p2[j]);
            Qs[(pr0 + 8) * 68 + cl + 1] = f2tf(p3[j]);
        }
        __syncthreads();

        // O += P @ V
#pragma unroll
        for (int ka = 0; ka < 8; ka++) {
            uint32_t pa[4];
            pa[0] = Qs[pr0 * 68 + ka * 8 + qd];
            pa[1] = Qs[(pr0 + 8) * 68 + ka * 8 + qd];
            pa[2] = Qs[pr0 * 68 + ka * 8 + qd + 4];
            pa[3] = Qs[(pr0 + 8) * 68 + ka * 8 + qd + 4];
#pragma unroll
            for (int j = 0; j < 8; j++) {
                uint32_t vb[2];
                vb[0] = Vs[(ka * 8 + qd) * 72 + j * 8 + gq];
                vb[1] = Vs[(ka * 8 + qd + 4) * 72 + j * 8 + gq];
                mma_tf32(oacc[j], pa, vb);
            }
        }
    }

    float inv0 = 1.f / lr0, inv1 = 1.f / lr1;
    float* Ob = g_ao + ((size_t)b * SEQ + row0) * DM + (size_t)h * DH;
#pragma unroll
    for (int j = 0; j < 8; j++) {
        int c = j * 8 + 2 * qd;
        *(float2*)&Ob[c]            = make_float2(oacc[j].x * inv0, oacc[j].y * inv0);
        *(float2*)&Ob[8 * DM + c]   = make_float2(oacc[j].z * inv1, oacc[j].w * inv1);
    }
}

// ---------------- launch ----------------
extern "C" void kernel_launch(void* const* d_in, const int* in_sizes, int n_in,
                              void* d_out, int out_size) {
    const float* x   = (const float*)d_in[0];
    const float* imp = (const float*)d_in[1];
    const float* Wc  = (const float*)d_in[2];
    const float* Wqk = (const float*)d_in[3];
    const float* Wv  = (const float*)d_in[4];
    const float* CN  = (const float*)d_in[5];
    const float* EQK = (const float*)d_in[6];
    const float* EV  = (const float*)d_in[7];
    const float* Wo  = (const float*)d_in[8];
    float* out = (float*)d_out;

    float *p_sc, *p_eqk, *p_ev, *p_h, *p_Q, *p_V, *p_ao;
    cudaGetSymbolAddress((void**)&p_sc,  g_sc);
    cudaGetSymbolAddress((void**)&p_eqk, g_eqk);
    cudaGetSymbolAddress((void**)&p_ev,  g_ev);
    cudaGetSymbolAddress((void**)&p_h,   g_h);
    cudaGetSymbolAddress((void**)&p_Q,   g_Q);
    cudaGetSymbolAddress((void**)&p_V,   g_V);
    cudaGetSymbolAddress((void**)&p_ao,  g_ao);

    static int smem_set = 0;
    const int flash_smem = (64 * 68 + 64 * 68 + 64 * 72) * (int)sizeof(uint32_t); // 53248
    if (!smem_set) {
        cudaFuncSetAttribute(flash_mma,
                             cudaFuncAttributeMaxDynamicSharedMemorySize, flash_smem);
        smem_set = 1;
    }

    // 1) router GEMM + fused softmax*importance
    router_gemm<<<dim3(1, (BATCH * SEQ) / 128), 256>>>(x, Wc, Wqk, Wv, imp);
    // 2) two-stage deterministic reduction over S
    reduce1_kernel<<<dim3(BATCH, 16), NW>>>();
    reduce2_kernel<<<BATCH, NW>>>();
    // 3) top-k + renorm
    topk_kernel<<<BATCH, 32>>>();
    // 4) sparse mixes
    build_sc_kernel <<<dim3((DM * RK) / 256, BATCH), 256>>>(CN);
    build_eqk_kernel<<<dim3((RK * DM) / 256, BATCH), 256>>>(EQK);
    build_ev_kernel <<<dim3((RK * DM) / 256, BATCH), 256>>>(EV);
    // 5) h = x @ sc   [1024 x 128 x 1024] per batch
    gemm_kernel<64><<<dim3(1, SEQ / 64, BATCH), 256>>>(
        x, p_sc, p_h, RK, DM,
        (long long)SEQ * DM, (long long)DM * RK, (long long)SEQ * RK);
    // 6) Q = h @ eqk  [1024 x 1024 x 128] per batch
    gemm_kernel<128><<<dim3(DM / 128, SEQ / 128, BATCH), 256>>>(
        p_h, p_eqk, p_Q, DM, RK,
        (long long)SEQ * RK, (long long)RK * DM, (long long)SEQ * DM);
    // 7) V = h @ ev
    gemm_kernel<128><<<dim3(DM / 128, SEQ / 128, BATCH), 256>>>(
        p_h, p_ev, p_V, DM, RK,
        (long long)SEQ * RK, (long long)RK * DM, (long long)SEQ * DM);
    // 8) flash attention (tf32 mma)
    flash_mma<<<dim3(SEQ / 64, NHEAD, BATCH), 128, flash_smem>>>();
    // 9) out = ao @ Wo^T (tf32 mma)
    gemm_nt_mma<<<dim3(DM / 128, (BATCH * SEQ) / 128), 256>>>(
        p_ao, Wo, out, DM, DM);
}

// round 5
// speedup vs baseline: 7.7411x; 1.1287x over previous
#include <cuda_runtime.h>
#include <math.h>
#include <stdint.h>

// ---------------- problem constants ----------------
#define DM    1024
#define SEQ   1024
#define BATCH 8
#define RK    128
#define NC    64
#define NQK   32
#define NV    32
#define KC    8
#define KQK   4
#define KV    6
#define NHEAD 16
#define DH    64
#define NW    128

// ---------------- device scratch ----------------
__device__ float g_prefw[BATCH * SEQ * NW];
__device__ float g_part[BATCH * 16 * NW];
__device__ int   g_cidx[BATCH * KC];
__device__ float g_cval[BATCH * KC];
__device__ int   g_qidx[BATCH * KQK];
__device__ float g_qval[BATCH * KQK];
__device__ int   g_vidx[BATCH * KV];
__device__ float g_vval[BATCH * KV];
__device__ float g_sc [BATCH * DM * RK];
__device__ float g_eqk[BATCH * RK * DM];
__device__ float g_ev [BATCH * RK * DM];
__device__ float g_h  [BATCH * SEQ * RK];
__device__ float g_Q  [BATCH * SEQ * DM];
__device__ float g_V  [BATCH * SEQ * DM];
__device__ float g_ao [BATCH * SEQ * DM];

// ---------------- tf32 helpers ----------------
__device__ __forceinline__ uint32_t f2tf(float x) {
    uint32_t r;
    asm("cvt.rna.tf32.f32 %0, %1;" : "=r"(r) : "f"(x));
    return r;
}
__device__ __forceinline__ void mma_tf32(float4& d, const uint32_t a[4], const uint32_t b[2]) {
    asm volatile(
        "mma.sync.aligned.m16n8k8.row.col.f32.tf32.tf32.f32 "
        "{%0,%1,%2,%3}, {%4,%5,%6,%7}, {%8,%9}, {%0,%1,%2,%3};\n"
        : "+f"(d.x), "+f"(d.y), "+f"(d.z), "+f"(d.w)
        : "r"(a[0]), "r"(a[1]), "r"(a[2]), "r"(a[3]), "r"(b[0]), "r"(b[1]));
}

// =====================================================================
// Router GEMM (fp32): logits = x @ [Wc;Wqk;Wv]^T, fused softmax*importance
// =====================================================================
__global__ __launch_bounds__(256, 2) void router_gemm(
    const float* __restrict__ x,  const float* __restrict__ Wc,
    const float* __restrict__ Wqk, const float* __restrict__ Wv,
    const float* __restrict__ imp)
{
    __shared__ float As[16][132];
    __shared__ float Bs[16][132];
    int tid = threadIdx.x, tx = tid & 15, ty = tid >> 4;
    int m0 = blockIdx.y * 128;
    float acc[8][8] = {};
    const int nkb = DM / 16;
    float4 pa[2], pb[2];

    auto LD = [&](int kb) {
#pragma unroll
        for (int i = 0; i < 2; i++) {
            int f = tid + i * 256; int r = f >> 2, q = f & 3;
            pa[i] = *(const float4*)&x[(size_t)(m0 + r) * DM + kb * 16 + q * 4];
        }
#pragma unroll
        for (int i = 0; i < 2; i++) {
            int f = tid + i * 256; int n = f >> 2, q = f & 3;
            const float* wrow = (n < NC) ? (Wc + (size_t)n * DM)
                              : (n < NC + NQK) ? (Wqk + (size_t)(n - NC) * DM)
                              : (Wv + (size_t)(n - NC - NQK) * DM);
            pb[i] = *(const float4*)&wrow[kb * 16 + q * 4];
        }
    };
    auto ST = [&]() {
#pragma unroll
        for (int i = 0; i < 2; i++) {
            int f = tid + i * 256; int r = f >> 2, q = f & 3;
            As[q*4+0][r] = pa[i].x; As[q*4+1][r] = pa[i].y;
            As[q*4+2][r] = pa[i].z; As[q*4+3][r] = pa[i].w;
        }
#pragma unroll
        for (int i = 0; i < 2; i++) {
            int f = tid + i * 256; int n = f >> 2, q = f & 3;
            Bs[q*4+0][n] = pb[i].x; Bs[q*4+1][n] = pb[i].y;
            Bs[q*4+2][n] = pb[i].z; Bs[q*4+3][n] = pb[i].w;
        }
    };

    LD(0); ST(); __syncthreads();
    for (int kb = 0; kb < nkb; kb++) {
        bool more = (kb + 1 < nkb);
        if (more) LD(kb + 1);
#pragma unroll
        for (int k = 0; k < 16; k++) {
            float a[8], b[8];
            *(float4*)&a[0] = *(const float4*)&As[k][ty * 4];
            *(float4*)&a[4] = *(const float4*)&As[k][64 + ty * 4];
            *(float4*)&b[0] = *(const float4*)&Bs[k][tx * 4];
            *(float4*)&b[4] = *(const float4*)&Bs[k][64 + tx * 4];
#pragma unroll
            for (int i = 0; i < 8; i++)
#pragma unroll
                for (int j = 0; j < 8; j++)
                    acc[i][j] = fmaf(a[i], b[j], acc[i][j]);
        }
        __syncthreads();
        if (more) { ST(); __syncthreads(); }
    }

#pragma unroll
    for (int i = 0; i < 8; i++) {
        int r = (i < 4) ? (ty * 4 + i) : (64 + ty * 4 + i - 4);
        int bs = m0 + r;
        float mC = fmaxf(fmaxf(acc[i][0], acc[i][1]), fmaxf(acc[i][2], acc[i][3]));
#pragma unroll
        for (int w = 1; w < 16; w <<= 1) mC = fmaxf(mC, __shfl_xor_sync(0xffffffffu, mC, w));
        float e0 = __expf(acc[i][0] - mC), e1 = __expf(acc[i][1] - mC);
        float e2 = __expf(acc[i][2] - mC), e3 = __expf(acc[i][3] - mC);
        float sC = e0 + e1 + e2 + e3;
#pragma unroll
        for (int w = 1; w < 16; w <<= 1) sC += __shfl_xor_sync(0xffffffffu, sC, w);

        float m2 = fmaxf(fmaxf(acc[i][4], acc[i][5]), fmaxf(acc[i][6], acc[i][7]));
#pragma unroll
        for (int w = 1; w < 8; w <<= 1) m2 = fmaxf(m2, __shfl_xor_sync(0xffffffffu, m2, w));
        float f0 = __expf(acc[i][4] - m2), f1 = __expf(acc[i][5] - m2);
        float f2 = __expf(acc[i][6] - m2), f3 = __expf(acc[i][7] - m2);
        float s2 = f0 + f1 + f2 + f3;
#pragma unroll
        for (int w = 1; w < 8; w <<= 1) s2 += __shfl_xor_sync(0xffffffffu, s2, w);

        float ip = imp[bs];
        float iC = ip / sC, i2 = ip / s2;
        float4 o0 = {e0 * iC, e1 * iC, e2 * iC, e3 * iC};
        float4 o1 = {f0 * i2, f1 * i2, f2 * i2, f3 * i2};
        *(float4*)&g_prefw[(size_t)bs * NW + tx * 4]      = o0;
        *(float4*)&g_prefw[(size_t)bs * NW + 64 + tx * 4] = o1;
    }
}

// ---------------- stage-1 reduction over S ----------------
__global__ void reduce1_kernel() {
    int b = blockIdx.x, chunk = blockIdx.y, t = threadIdx.x;
    const float* p = g_prefw + ((size_t)b * SEQ + chunk * 64) * NW + t;
    float s = 0.f;
#pragma unroll 8
    for (int i = 0; i < 64; i++) s += p[(size_t)i * NW];
    g_part[(b * 16 + chunk) * NW + t] = s;
}

// ---------------- fused stage-2 reduction + top-k + renormalize ----------------
__device__ void topk_store(const float* v, int n, int k, int* oidx, float* oval) {
    float tmp[64];
    for (int i = 0; i < n; i++) tmp[i] = v[i];
    float sum = 0.f;
    for (int j = 0; j < k; j++) {
        int bi = 0; float bv = tmp[0];
        for (int i = 1; i < n; i++) { if (tmp[i] > bv) { bv = tmp[i]; bi = i; } }
        oidx[j] = bi; oval[j] = bv; sum += bv;
        tmp[bi] = -1e30f;
    }
    float inv = 1.f / (sum + 1e-8f);
    for (int j = 0; j < k; j++) oval[j] *= inv;
}
__global__ void reduce2_topk_kernel() {
    __shared__ float acc[NW];
    int b = blockIdx.x, t = threadIdx.x;
    float s = 0.f;
#pragma unroll
    for (int c = 0; c < 16; c++) s += g_part[(b * 16 + c) * NW + t];
    acc[t] = s;
    __syncthreads();
    if (t == 0)      topk_store(acc,            NC,  KC,  g_cidx + b * KC,  g_cval + b * KC);
    else if (t == 1) topk_store(acc + NC,       NQK, KQK, g_qidx + b * KQK, g_qval + b * KQK);
    else if (t == 2) topk_store(acc + NC + NQK, NV,  KV,  g_vidx + b * KV,  g_vval + b * KV);
}

// ---------------- sparse weighted mixes ----------------
__global__ void build_sc_kernel(const float* __restrict__ CN) {
    int b = blockIdx.y;
    int i = blockIdx.x * blockDim.x + threadIdx.x;
    float s = 0.f;
#pragma unroll
    for (int j = 0; j < KC; j++) {
        int n = g_cidx[b * KC + j];
        s = fmaf(g_cval[b * KC + j], CN[(size_t)n * (DM * RK) + i], s);
    }
    g_sc[(size_t)b * (DM * RK) + i] = s;
}
__global__ void build_eqk_kernel(const float* __restrict__ E) {
    int b = blockIdx.y;
    int i = blockIdx.x * blockDim.x + threadIdx.x;
    float s = 0.f;
#pragma unroll
    for (int j = 0; j < KQK; j++) {
        int n = g_qidx[b * KQK + j];
        s = fmaf(g_qval[b * KQK + j], E[(size_t)n * (RK * DM) + i], s);
    }
    g_eqk[(size_t)b * (RK * DM) + i] = s;
}
__global__ void build_ev_kernel(const float* __restrict__ E) {
    int b = blockIdx.y;
    int i = blockIdx.x * blockDim.x + threadIdx.x;
    float s = 0.f;
#pragma unroll
    for (int j = 0; j < KV; j++) {
        int n = g_vidx[b * KV + j];
        s = fmaf(g_vval[b * KV + j], E[(size_t)n * (RK * DM) + i], s);
    }
    g_ev[(size_t)b * (RK * DM) + i] = s;
}

// =====================================================================
// tf32 GEMM (nn): C = A(MxK) @ B(KxN), batched via blockIdx.z strides.
// BM=BN=128, BK=16, 8 warps (4m x 2n), warp tile 32x64 (2x8 atoms).
// A staged [m][k] pad 20; B staged [k][n] pad 136 (conflict-free b-frags).
// =====================================================================
__global__ __launch_bounds__(256, 2) void gemm_nn_mma(
    const float* __restrict__ A, const float* __restrict__ B,
    float* __restrict__ C, int N, int K,
    long long sA, long long sB, long long sC)
{
    __shared__ uint32_t As[128 * 20];
    __shared__ uint32_t Bs[16 * 136];
    A += (long long)blockIdx.z * sA;
    B += (long long)blockIdx.z * sB;
    C += (long long)blockIdx.z * sC;
    int tid = threadIdx.x, lane = tid & 31, w = tid >> 5;
    int gq = lane >> 2, qd = lane & 3;
    int wm = w & 3, wn = w >> 2;
    int m0 = blockIdx.y * 128, n0 = blockIdx.x * 128;

    float4 acc[2][8];
#pragma unroll
    for (int i = 0; i < 2; i++)
#pragma unroll
        for (int j = 0; j < 8; j++) acc[i][j] = make_float4(0.f, 0.f, 0.f, 0.f);

    const int nkb = K / 16;
    float4 pa[2], pb[2];

    auto LD = [&](int kb) {
#pragma unroll
        for (int i = 0; i < 2; i++) {
            int f = tid + i * 256; int r = f >> 2, q = f & 3;
            pa[i] = *(const float4*)&A[(size_t)(m0 + r) * K + kb * 16 + q * 4];
        }
#pragma unroll
        for (int i = 0; i < 2; i++) {
            int f = tid + i * 256; int r = f >> 5, c = f & 31;
            pb[i] = *(const float4*)&B[(size_t)(kb * 16 + r) * N + n0 + c * 4];
        }
    };
    auto ST = [&]() {
#pragma unroll
        for (int i = 0; i < 2; i++) {
            int f = tid + i * 256; int r = f >> 2, q = f & 3;
            uint32_t* da = &As[r * 20 + q * 4];
            da[0] = f2tf(pa[i].x); da[1] = f2tf(pa[i].y);
            da[2] = f2tf(pa[i].z); da[3] = f2tf(pa[i].w);
        }
#pragma unroll
        for (int i = 0; i < 2; i++) {
            int f = tid + i * 256; int r = f >> 5, c = f & 31;
            uint32_t* db = &Bs[r * 136 + c * 4];
            db[0] = f2tf(pb[i].x); db[1] = f2tf(pb[i].y);
            db[2] = f2tf(pb[i].z); db[3] = f2tf(pb[i].w);
        }
    };

    LD(0); ST(); __syncthreads();
    for (int kb = 0; kb < nkb; kb++) {
        bool more = (kb + 1 < nkb);
        if (more) LD(kb + 1);
#pragma unroll
        for (int s = 0; s < 2; s++) {
            int kbs = s * 8;
            uint32_t af[2][4];
#pragma unroll
            for (int i = 0; i < 2; i++) {
                int r = wm * 32 + i * 16 + gq;
                af[i][0] = As[r * 20 + kbs + qd];
                af[i][1] = As[(r + 8) * 20 + kbs + qd];
                af[i][2] = As[r * 20 + kbs + qd + 4];
                af[i][3] = As[(r + 8) * 20 + kbs + qd + 4];
            }
            uint32_t bf[8][2];
#pragma unroll
            for (int j = 0; j < 8; j++) {
                int n = wn * 64 + j * 8 + gq;
                bf[j][0] = Bs[(kbs + qd) * 136 + n];
                bf[j][1] = Bs[(kbs + qd + 4) * 136 + n];
            }
#pragma unroll
            for (int i = 0; i < 2; i++)
#pragma unroll
                for (int j = 0; j < 8; j++)
                    mma_tf32(acc[i][j], af[i], bf[j]);
        }
        __syncthreads();
        if (more) { ST(); __syncthreads(); }
    }

#pragma unroll
    for (int i = 0; i < 2; i++) {
        int r0 = m0 + wm * 32 + i * 16 + gq;
#pragma unroll
        for (int j = 0; j < 8; j++) {
            int c0 = n0 + wn * 64 + j * 8 + 2 * qd;
            *(float2*)&C[(size_t)r0 * N + c0]       = make_float2(acc[i][j].x, acc[i][j].y);
            *(float2*)&C[(size_t)(r0 + 8) * N + c0] = make_float2(acc[i][j].z, acc[i][j].w);
        }
    }
}

// =====================================================================
// Out-projection: C = A(8192x1024) @ Wo^T via tf32 mma.sync. (nt)
// =====================================================================
__global__ __launch_bounds__(256, 2) void gemm_nt_mma(
    const float* __restrict__ A, const float* __restrict__ B,
    float* __restrict__ C, int N, int K)
{
    __shared__ uint32_t As[128 * 20];
    __shared__ uint32_t Bs[128 * 20];
    int tid = threadIdx.x, lane = tid & 31, w = tid >> 5;
    int gq = lane >> 2, qd = lane & 3;
    int wm = w & 3, wn = w >> 2;
    int m0 = blockIdx.y * 128, n0 = blockIdx.x * 128;

    float4 acc[2][8];
#pragma unroll
    for (int i = 0; i < 2; i++)
#pragma unroll
        for (int j = 0; j < 8; j++) acc[i][j] = make_float4(0.f, 0.f, 0.f, 0.f);

    const int nkb = K / 16;
    float4 pa[2], pb[2];

    auto LD = [&](int kb) {
#pragma unroll
        for (int i = 0; i < 2; i++) {
            int f = tid + i * 256; int r = f >> 2, q = f & 3;
            pa[i] = *(const float4*)&A[(size_t)(m0 + r) * K + kb * 16 + q * 4];
            pb[i] = *(const float4*)&B[(size_t)(n0 + r) * K + kb * 16 + q * 4];
        }
    };
    auto ST = [&]() {
#pragma unroll
        for (int i = 0; i < 2; i++) {
            int f = tid + i * 256; int r = f >> 2, q = f & 3;
            uint32_t* da = &As[r * 20 + q * 4];
            da[0] = f2tf(pa[i].x); da[1] = f2tf(pa[i].y);
            da[2] = f2tf(pa[i].z); da[3] = f2tf(pa[i].w);
            uint32_t* db = &Bs[r * 20 + q * 4];
            db[0] = f2tf(pb[i].x); db[1] = f2tf(pb[i].y);
            db[2] = f2tf(pb[i].z); db[3] = f2tf(pb[i].w);
        }
    };

    LD(0); ST(); __syncthreads();
    for (int kb = 0; kb < nkb; kb++) {
        bool more = (kb + 1 < nkb);
        if (more) LD(kb + 1);
#pragma unroll
        for (int s = 0; s < 2; s++) {
            int kbs = s * 8;
            uint32_t af[2][4];
#pragma unroll
            for (int i = 0; i < 2; i++) {
                int r = wm * 32 + i * 16 + gq;
                af[i][0] = As[r * 20 + kbs + qd];
                af[i][1] = As[(r + 8) * 20 + kbs + qd];
                af[i][2] = As[r * 20 + kbs + qd + 4];
                af[i][3] = As[(r + 8) * 20 + kbs + qd + 4];
            }
            uint32_t bf[8][2];
#pragma unroll
            for (int j = 0; j < 8; j++) {
                int n = wn * 64 + j * 8 + gq;
                bf[j][0] = Bs[n * 20 + kbs + qd];
                bf[j][1] = Bs[n * 20 + kbs + qd + 4];
            }
#pragma unroll
            for (int i = 0; i < 2; i++)
#pragma unroll
                for (int j = 0; j < 8; j++)
                    mma_tf32(acc[i][j], af[i], bf[j]);
        }
        __syncthreads();
        if (more) { ST(); __syncthreads(); }
    }

#pragma unroll
    for (int i = 0; i < 2; i++) {
        int r0 = m0 + wm * 32 + i * 16 + gq;
#pragma unroll
        for (int j = 0; j < 8; j++) {
            int c0 = n0 + wn * 64 + j * 8 + 2 * qd;
            *(float2*)&C[(size_t)r0 * N + c0]       = make_float2(acc[i][j].x, acc[i][j].y);
            *(float2*)&C[(size_t)(r0 + 8) * N + c0] = make_float2(acc[i][j].z, acc[i][j].w);
        }
    }
}

// =====================================================================
// Flash attention (K==Q), causal, tf32 mma. 64-row q-tiles, 4 warps.
// =====================================================================
__global__ __launch_bounds__(128) void flash_mma() {
    extern __shared__ uint32_t sm[];
    uint32_t* Qs = sm;                 // 64 x 68 (reused for P)
    uint32_t* Ks = sm + 64 * 68;
    uint32_t* Vs = sm + 2 * 64 * 68;   // 64 x 72

    int qt = gridDim.x - 1 - blockIdx.x;
    int h = blockIdx.y, b = blockIdx.z;
    int tid = threadIdx.x, lane = tid & 31, w = tid >> 5;
    int gq = lane >> 2, qd = lane & 3;

    const float* Qb = g_Q + (size_t)b * SEQ * DM + (size_t)h * DH;
    const float* Vb = g_V + (size_t)b * SEQ * DM + (size_t)h * DH;

    for (int f = tid; f < 64 * 16; f += 128) {
        int r = f >> 4, q = f & 15;
        float4 v = *(const float4*)&Qb[(size_t)(qt * 64 + r) * DM + q * 4];
        uint32_t* d = &Qs[r * 68 + q * 4];
        d[0] = f2tf(v.x); d[1] = f2tf(v.y); d[2] = f2tf(v.z); d[3] = f2tf(v.w);
    }
    __syncthreads();

    uint32_t qa[8][4];
    int qr = w * 16 + gq;
#pragma unroll
    for (int ka = 0; ka < 8; ka++) {
        qa[ka][0] = Qs[qr * 68 + ka * 8 + qd];
        qa[ka][1] = Qs[(qr + 8) * 68 + ka * 8 + qd];
        qa[ka][2] = Qs[qr * 68 + ka * 8 + qd + 4];
        qa[ka][3] = Qs[(qr + 8) * 68 + ka * 8 + qd + 4];
    }

    float mr0 = -1e30f, mr1 = -1e30f, lr0 = 0.f, lr1 = 0.f;
    float4 oacc[8];
#pragma unroll
    for (int j = 0; j < 8; j++) oacc[j] = make_float4(0.f, 0.f, 0.f, 0.f);

    int row0 = qt * 64 + w * 16 + gq;
    int row1 = row0 + 8;
    const float scale = 0.125f;

    for (int kt = 0; kt <= qt; kt++) {
        __syncthreads();
        for (int f = tid; f < 64 * 16; f += 128) {
            int r = f >> 4, q = f & 15;
            float4 kv = *(const float4*)&Qb[(size_t)(kt * 64 + r) * DM + q * 4];
            uint32_t* dk = &Ks[r * 68 + q * 4];
            dk[0] = f2tf(kv.x); dk[1] = f2tf(kv.y); dk[2] = f2tf(kv.z); dk[3] = f2tf(kv.w);
            float4 vv = *(const float4*)&Vb[(size_t)(kt * 64 + r) * DM + q * 4];
            uint32_t* dv = &Vs[r * 72 + q * 4];
            dv[0] = f2tf(vv.x); dv[1] = f2tf(vv.y); dv[2] = f2tf(vv.z); dv[3] = f2tf(vv.w);
        }
        __syncthreads();

        float4 sacc[8];
#pragma unroll
        for (int j = 0; j < 8; j++) sacc[j] = make_float4(0.f, 0.f, 0.f, 0.f);
#pragma unroll
        for (int ka = 0; ka < 8; ka++) {
#pragma unroll
            for (int j = 0; j < 8; j++) {
                uint32_t bb[2];
                bb[0] = Ks[(j * 8 + gq) * 68 + ka * 8 + qd];
                bb[1] = Ks[(j * 8 + gq) * 68 + ka * 8 + qd + 4];
                mma_tf32(sacc[j], qa[ka], bb);
            }
        }

        bool diag = (kt == qt);
        float p0[8], p1[8], p2[8], p3[8];
        float mx0 = -1e30f, mx1 = -1e30f;
#pragma unroll
        for (int j = 0; j < 8; j++) {
            int col = kt * 64 + j * 8 + 2 * qd;
            float c0 = sacc[j].x * scale, c1 = sacc[j].y * scale;
            float c2 = sacc[j].z * scale, c3 = sacc[j].w * scale;
            if (diag) {
                if (col     > row0) c0 = -1e30f;
                if (col + 1 > row0) c1 = -1e30f;
                if (col     > row1) c2 = -1e30f;
                if (col + 1 > row1) c3 = -1e30f;
            }
            p0[j] = c0; p1[j] = c1; p2[j] = c2; p3[j] = c3;
            mx0 = fmaxf(mx0, fmaxf(c0, c1));
            mx1 = fmaxf(mx1, fmaxf(c2, c3));
        }
        mx0 = fmaxf(mx0, __shfl_xor_sync(0xffffffffu, mx0, 1));
        mx0 = fmaxf(mx0, __shfl_xor_sync(0xffffffffu, mx0, 2));
        mx1 = fmaxf(mx1, __shfl_xor_sync(0xffffffffu, mx1, 1));
        mx1 = fmaxf(mx1, __shfl_xor_sync(0xffffffffu, mx1, 2));

        float mn0 = fmaxf(mr0, mx0), mn1 = fmaxf(mr1, mx1);
        float al0 = __expf(mr0 - mn0), al1 = __expf(mr1 - mn1);
        float ps0 = 0.f, ps1 = 0.f;
#pragma unroll
        for (int j = 0; j < 8; j++) {
            p0[j] = __expf(p0[j] - mn0); p1[j] = __expf(p1[j] - mn0);
            p2[j] = __expf(p2[j] - mn1); p3[j] = __expf(p3[j] - mn1);
            ps0 += p0[j] + p1[j];
            ps1 += p2[j] + p3[j];
        }
        ps0 += __shfl_xor_sync(0xffffffffu, ps0, 1);
        ps0 += __shfl_xor_sync(0xffffffffu, ps0, 2);
        ps1 += __shfl_xor_sync(0xffffffffu, ps1, 1);
        ps1 += __shfl_xor_sync(0xffffffffu, ps1, 2);

        lr0 = lr0 * al0 + ps0; lr1 = lr1 * al1 + ps1;
        mr0 = mn0; mr1 = mn1;
#pragma unroll
        for (int j = 0; j < 8; j++) {
            oacc[j].x *= al0; oacc[j].y *= al0;
            oacc[j].z *= al1; oacc[j].w *= al1;
        }

        int pr0 = w * 16 + gq;
#pragma unroll
        for (int j = 0; j < 8; j++) {
            int cl = j * 8 + 2 * qd;
            Qs[pr0 * 68 + cl]           = f2tf(p0[j]);
            Qs[pr0 * 68 + cl + 1]       = f2tf(p1[j]);
            Qs[(pr0 + 8) * 68 + cl]     = f2tf(p2[j]);
            Qs[(pr0 + 8) * 68 + cl + 1] = f2tf(p3[j]);
        }
        __syncthreads();

#pragma unroll
        for (int ka = 0; ka < 8; ka++) {
            uint32_t pa[4];
            pa[0] = Qs[pr0 * 68 + ka * 8 + qd];
            pa[1] = Qs[(pr0 + 8) * 68 + ka * 8 + qd];
            pa[2] = Qs[pr0 * 68 + ka * 8 + qd + 4];
            pa[3] = Qs[(pr0 + 8) * 68 + ka * 8 + qd + 4];
#pragma unroll
            for (int j = 0; j < 8; j++) {
                uint32_t vb[2];
                vb[0] = Vs[(ka * 8 + qd) * 72 + j * 8 + gq];
                vb[1] = Vs[(ka * 8 + qd + 4) * 72 + j * 8 + gq];
                mma_tf32(oacc[j], pa, vb);
            }
        }
    }

    float inv0 = 1.f / lr0, inv1 = 1.f / lr1;
    float* Ob = g_ao + ((size_t)b * SEQ + row0) * DM + (size_t)h * DH;
#pragma unroll
    for (int j = 0; j < 8; j++) {
        int c = j * 8 + 2 * qd;
        *(float2*)&Ob[c]            = make_float2(oacc[j].x * inv0, oacc[j].y * inv0);
        *(float2*)&Ob[8 * DM + c]   = make_float2(oacc[j].z * inv1, oacc[j].w * inv1);
    }
}

// ---------------- launch ----------------
extern "C" void kernel_launch(void* const* d_in, const int* in_sizes, int n_in,
                              void* d_out, int out_size) {
    const float* x   = (const float*)d_in[0];
    const float* imp = (const float*)d_in[1];
    const float* Wc  = (const float*)d_in[2];
    const float* Wqk = (const float*)d_in[3];
    const float* Wv  = (const float*)d_in[4];
    const float* CN  = (const float*)d_in[5];
    const float* EQK = (const float*)d_in[6];
    const float* EV  = (const float*)d_in[7];
    const float* Wo  = (const float*)d_in[8];
    float* out = (float*)d_out;

    float *p_sc, *p_eqk, *p_ev, *p_h, *p_Q, *p_V, *p_ao;
    cudaGetSymbolAddress((void**)&p_sc,  g_sc);
    cudaGetSymbolAddress((void**)&p_eqk, g_eqk);
    cudaGetSymbolAddress((void**)&p_ev,  g_ev);
    cudaGetSymbolAddress((void**)&p_h,   g_h);
    cudaGetSymbolAddress((void**)&p_Q,   g_Q);
    cudaGetSymbolAddress((void**)&p_V,   g_V);
    cudaGetSymbolAddress((void**)&p_ao,  g_ao);

    static int smem_set = 0;
    const int flash_smem = (64 * 68 + 64 * 68 + 64 * 72) * (int)sizeof(uint32_t); // 53248
    if (!smem_set) {
        cudaFuncSetAttribute(flash_mma,
                             cudaFuncAttributeMaxDynamicSharedMemorySize, flash_smem);
        smem_set = 1;
    }

    // 1) router GEMM + fused softmax*importance
    router_gemm<<<dim3(1, (BATCH * SEQ) / 128), 256>>>(x, Wc, Wqk, Wv, imp);
    // 2) reduction over S + top-k (fused)
    reduce1_kernel<<<dim3(BATCH, 16), NW>>>();
    reduce2_topk_kernel<<<BATCH, NW>>>();
    // 3) sparse mixes
    build_sc_kernel <<<dim3((DM * RK) / 256, BATCH), 256>>>(CN);
    build_eqk_kernel<<<dim3((RK * DM) / 256, BATCH), 256>>>(EQK);
    build_ev_kernel <<<dim3((RK * DM) / 256, BATCH), 256>>>(EV);
    // 4) h = x @ sc   [1024 x 128 x 1024] per batch (tf32)
    gemm_nn_mma<<<dim3(1, SEQ / 128, BATCH), 256>>>(
        x, p_sc, p_h, RK, DM,
        (long long)SEQ * DM, (long long)DM * RK, (long long)SEQ * RK);
    // 5) Q = h @ eqk  [1024 x 1024 x 128] per batch (tf32)
    gemm_nn_mma<<<dim3(DM / 128, SEQ / 128, BATCH), 256>>>(
        p_h, p_eqk, p_Q, DM, RK,
        (long long)SEQ * RK, (long long)RK * DM, (long long)SEQ * DM);
    // 6) V = h @ ev (tf32)
    gemm_nn_mma<<<dim3(DM / 128, SEQ / 128, BATCH), 256>>>(
        p_h, p_ev, p_V, DM, RK,
        (long long)SEQ * RK, (long long)RK * DM, (long long)SEQ * DM);
    // 7) flash attention (tf32 mma)
    flash_mma<<<dim3(SEQ / 64, NHEAD, BATCH), 128, flash_smem>>>();
    // 8) out = ao @ Wo^T (tf32 mma)
    gemm_nt_mma<<<dim3(DM / 128, (BATCH * SEQ) / 128), 256>>>(
        p_ao, Wo, out, DM, DM);
}